// round 4
// baseline (speedup 1.0000x reference)
#include <cuda_runtime.h>

// 2-layer LSTM + linear head + clip. B=256 T=2048 I=32 H=64.
// Phase 1 (xg_kernel): precompute xg[t][b][gate] = x@Wih0^T + b_ih0 + b_hh0 for
//   all timesteps (parallel GEMM) into 512MB __device__ scratch, stored in the
//   loop kernel's permuted gate order -> coalesced per-step loads.
// Phase 2 (lstm2_kernel): persistent CTA (256 thr) = 2 batch elements over all
//   2048 steps. Thread tid owns gate row r = (tid%4)*64 + tid/4; lane quad = 4
//   gates of one hidden unit -> cell via warp shuffle, c state in regs.
//   Packed fma.rn.f32x2 column pairs. Layer-1 recurrent weights (32 packs) +
//   40 of 64 layer-2 packs in regs; 24 layer-2 packs/thread in smem at 26-ull
//   stride (conflict-free 4-phase LDS.128). 2 barriers/step, h2 double-buffered.

#define TT 2048
#define NB 256
#define NI 32
#define RWSTR 26   // per-thread smem weight stride in ull (24 used)

typedef unsigned long long ull;

__device__ float g_xg[134217728];   // [T][B][256] fp32, permuted gate order

__device__ __forceinline__ float sigmf(float v) {
    return __fdividef(1.f, 1.f + __expf(-v));
}
__device__ __forceinline__ void fma2(ull& d, ull a, ull b) {
    asm("fma.rn.f32x2 %0, %1, %2, %0;" : "+l"(d) : "l"(a), "l"(b));
}
__device__ __forceinline__ ull add2(ull a, ull b) {
    ull r; asm("add.rn.f32x2 %0, %1, %2;" : "=l"(r) : "l"(a), "l"(b)); return r;
}
__device__ __forceinline__ float2 unpk(ull v) {
    float2 r; asm("mov.b64 {%0, %1}, %2;" : "=f"(r.x), "=f"(r.y) : "l"(v)); return r;
}
__device__ __forceinline__ ull pk(float a, float b) {
    ull r; asm("mov.b64 %0, {%1, %2};" : "=l"(r) : "f"(a), "f"(b)); return r;
}
// gates pre-activated: gi,gf,go = sigmoid, gg = tanh
__device__ __forceinline__ float cell_rest(float gi, float gf, float gg, float go, float& c) {
    c = fmaf(gf, c, gi * gg);
    return go * fmaf(2.f, sigmf(2.f * c), -1.f);   // o * tanh(c)
}

// ---------------- Phase 1: xg precompute ----------------
// CTA tile: 4 batches x 64 timesteps. grid = (2048/64)*(256/4) = 2048 CTAs.
__global__ void __launch_bounds__(256, 1)
xg_kernel(const float* __restrict__ x,
          const float* __restrict__ Wih0,
          const float* __restrict__ bih0, const float* __restrict__ bhh0)
{
    __shared__ float xt[4][64 * NI];   // 32 KB
    const int tid = threadIdx.x;
    const int t0 = (blockIdx.x & 31) * 64;
    const int b0 = (blockIdx.x >> 5) * 4;
    const int r  = ((tid & 3) << 6) | (tid >> 2);

    // load x tile (coalesced)
    #pragma unroll
    for (int b = 0; b < 4; b++) {
        const float4* src = (const float4*)(x + ((size_t)(b0 + b) * TT + t0) * NI);
        float4* dst = (float4*)xt[b];
        for (int i = tid; i < 64 * NI / 4; i += 256) dst[i] = src[i];
    }

    ull w[16];
    {
        const ulonglong2* W = (const ulonglong2*)(Wih0 + r * NI);
        #pragma unroll
        for (int k = 0; k < 8; k++) { ulonglong2 v = W[k]; w[2*k] = v.x; w[2*k+1] = v.y; }
    }
    const float bias = bih0[r] + bhh0[r];
    __syncthreads();

    #pragma unroll
    for (int b = 0; b < 4; b++) {
        float* dst = g_xg + ((size_t)t0 * NB + (b0 + b)) * 256 + tid;
        #pragma unroll 4
        for (int t = 0; t < 64; t++) {
            const ulonglong2* v = (const ulonglong2*)(xt[b] + t * NI);
            ull aA = pk(bias, 0.f), aB = 0ull;
            #pragma unroll
            for (int c = 0; c < 8; c++) {
                ulonglong2 u = v[c];
                fma2(aA, w[2*c],   u.x);
                fma2(aB, w[2*c+1], u.y);
            }
            float2 s = unpk(add2(aA, aB));
            dst[(size_t)t * NB * 256] = s.x + s.y;
        }
    }
}

// ---------------- Phase 2: recurrent loop ----------------
__global__ void __launch_bounds__(256, 1)
lstm2_kernel(const float* __restrict__ Whh0,
             const float* __restrict__ Wih1, const float* __restrict__ Whh1,
             const float* __restrict__ bih1, const float* __restrict__ bhh1,
             const float* __restrict__ Wout, const float* __restrict__ bOut,
             float* __restrict__ out)
{
    extern __shared__ ull smu[];
    // [0 .. 256*RWSTR) per-thread layer-2 weight packs (24 used of 26)
    float* v1   = (float*)(smu + 256 * RWSTR);  // [2][64] h1 (single-buffered)
    float* h2b  = v1 + 128;                     // [2][2][64] h2 double buffer
    float* ybuf = h2b + 256;                    // [2][8] per-warp y partials

    const int tid  = threadIdx.x;
    const int lane = tid & 31;
    const int wrp  = tid >> 5;
    const int q    = tid & 3;                   // gate: 0=i 1=f 2=g 3=o
    const int r    = (q << 6) | (tid >> 2);
    const int h    = tid >> 2;
    const int bb   = blockIdx.x << 1;

    const ull b2p = pk(bih1[r] + bhh1[r], 0.f);
    const float wo = (q == 0) ? Wout[h] : 0.f;
    const float bo = bOut[0];
    const float kml = (q == 2) ? 2.f : 1.f;     // act = msc*sigm(kml*A)+mad
    const float msc = (q == 2) ? 2.f : 1.f;
    const float mad = (q == 2) ? -1.f : 0.f;

    // ---- weights ----
    ull w1p[32];   // Whh0 row
    {
        const ulonglong2* B = (const ulonglong2*)(Whh0 + r * 64);
        #pragma unroll
        for (int k = 0; k < 16; k++) { ulonglong2 v = B[k]; w1p[2*k] = v.x; w1p[2*k+1] = v.y; }
    }
    ull w2p[40];   // Wih1 row (32 packs) + Whh1 cols 0..15 (8 packs)
    {
        const ulonglong2* A = (const ulonglong2*)(Wih1 + r * 64);
        #pragma unroll
        for (int k = 0; k < 16; k++) { ulonglong2 v = A[k]; w2p[2*k] = v.x; w2p[2*k+1] = v.y; }
        const ulonglong2* B = (const ulonglong2*)(Whh1 + r * 64);
        #pragma unroll
        for (int k = 0; k < 4; k++) { ulonglong2 v = B[k]; w2p[32+2*k] = v.x; w2p[33+2*k] = v.y; }
        ulonglong2* RWi = (ulonglong2*)(smu + tid * RWSTR);   // Whh1 cols 16..63
        #pragma unroll
        for (int k = 0; k < 12; k++) RWi[k] = B[4 + k];
    }

    // zero v1 / h2b / ybuf
    for (int i = tid; i < 128 + 256 + 16; i += 256) v1[i] = 0.f;
    __syncthreads();

    float c10 = 0.f, c11 = 0.f, c20 = 0.f, c21 = 0.f;
    const ulonglong2* RW = (const ulonglong2*)(smu + tid * RWSTR);
    const unsigned FULL = 0xffffffffu;
    const int base = lane & ~3;

    // current-step xg (t = 0)
    float xc0, xc1;
    {
        const float* g0 = g_xg + (size_t)bb * 256 + tid;
        xc0 = g0[0]; xc1 = g0[256];
    }

    for (int t = 0; t < TT; ++t) {
        // prefetch xg for t+1
        float xn0 = 0.f, xn1 = 0.f;
        if (t + 1 < TT) {
            const float* gp = g_xg + ((size_t)(t + 1) * NB + bb) * 256 + tid;
            xn0 = gp[0]; xn1 = gp[256];
        }

        // ---- layer-1: recurrent part only (xg folded into init) ----
        ull a0A = pk(xc0, 0.f), a0B = 0ull, a1A = pk(xc1, 0.f), a1B = 0ull;
        {
            const ulonglong2* Va = (const ulonglong2*)v1;
            const ulonglong2* Vb = (const ulonglong2*)(v1 + 64);
            #pragma unroll
            for (int c = 0; c < 16; ++c) {
                ulonglong2 va = Va[c], vb = Vb[c];
                fma2(a0A, w1p[2*c],   va.x);
                fma2(a0B, w1p[2*c+1], va.y);
                fma2(a1A, w1p[2*c],   vb.x);
                fma2(a1B, w1p[2*c+1], vb.y);
            }
        }
        float2 s0 = unpk(add2(a0A, a0B));
        float2 s1 = unpk(add2(a1A, a1B));
        float act0 = fmaf(msc, sigmf(kml * (s0.x + s0.y)), mad);
        float act1 = fmaf(msc, sigmf(kml * (s1.x + s1.y)), mad);
        float gi0 = __shfl_sync(FULL, act0, base + 0);
        float gf0 = __shfl_sync(FULL, act0, base + 1);
        float gg0 = __shfl_sync(FULL, act0, base + 2);
        float go0 = __shfl_sync(FULL, act0, base + 3);
        float gi1 = __shfl_sync(FULL, act1, base + 0);
        float gf1 = __shfl_sync(FULL, act1, base + 1);
        float gg1 = __shfl_sync(FULL, act1, base + 2);
        float go1 = __shfl_sync(FULL, act1, base + 3);
        float h10 = cell_rest(gi0, gf0, gg0, go0, c10);
        float h11 = cell_rest(gi1, gf1, gg1, go1, c11);

        __syncthreads();   // S1: all reads of v1 (h1_{t-1}) done

        if (q == 0) { v1[h] = h10; v1[64 + h] = h11; }
        if (tid < 2 && t > 0) {     // finalize y_{t-1} off critical path
            float s = bo;
            #pragma unroll
            for (int k = 0; k < 8; k++) s += ybuf[tid * 8 + k];
            out[(size_t)(bb + tid) * TT + (t - 1)] = fminf(fmaxf(s, 0.f), 1.f);
        }

        __syncthreads();   // S2: h1_t published

        // ---- layer-2 ----
        ull b0A = b2p, b0B = 0ull, b1A = b2p, b1B = 0ull;
        {
            const ulonglong2* U0 = (const ulonglong2*)v1;          // h1_t
            const ulonglong2* U1 = (const ulonglong2*)(v1 + 64);
            const float* h2p = h2b + ((t + 1) & 1) * 128;          // h2_{t-1}
            const ulonglong2* P0 = (const ulonglong2*)h2p;
            const ulonglong2* P1 = (const ulonglong2*)(h2p + 64);
            #pragma unroll
            for (int c = 0; c < 16; ++c) {          // h1 cols 0..63 (reg packs)
                ulonglong2 ua = U0[c], ub = U1[c];
                fma2(b0A, w2p[2*c],   ua.x);
                fma2(b0B, w2p[2*c+1], ua.y);
                fma2(b1A, w2p[2*c],   ub.x);
                fma2(b1B, w2p[2*c+1], ub.y);
            }
            #pragma unroll
            for (int c = 0; c < 4; ++c) {           // h2 cols 0..15 (reg packs)
                ulonglong2 ua = P0[c], ub = P1[c];
                fma2(b0A, w2p[32+2*c], ua.x);
                fma2(b0B, w2p[33+2*c], ua.y);
                fma2(b1A, w2p[32+2*c], ub.x);
                fma2(b1B, w2p[33+2*c], ub.y);
            }
            #pragma unroll
            for (int c = 0; c < 12; ++c) {          // h2 cols 16..63 (smem packs)
                ulonglong2 wv = RW[c];
                ulonglong2 ua = P0[4 + c], ub = P1[4 + c];
                fma2(b0A, wv.x, ua.x);
                fma2(b0B, wv.y, ua.y);
                fma2(b1A, wv.x, ub.x);
                fma2(b1B, wv.y, ub.y);
            }
        }
        float2 u0 = unpk(add2(b0A, b0B));
        float2 u1 = unpk(add2(b1A, b1B));
        float bact0 = fmaf(msc, sigmf(kml * (u0.x + u0.y)), mad);
        float bact1 = fmaf(msc, sigmf(kml * (u1.x + u1.y)), mad);
        float Gi0 = __shfl_sync(FULL, bact0, base + 0);
        float Gf0 = __shfl_sync(FULL, bact0, base + 1);
        float Gg0 = __shfl_sync(FULL, bact0, base + 2);
        float Go0 = __shfl_sync(FULL, bact0, base + 3);
        float Gi1 = __shfl_sync(FULL, bact1, base + 0);
        float Gf1 = __shfl_sync(FULL, bact1, base + 1);
        float Gg1 = __shfl_sync(FULL, bact1, base + 2);
        float Go1 = __shfl_sync(FULL, bact1, base + 3);
        float h20 = cell_rest(Gi0, Gf0, Gg0, Go0, c20);
        float h21 = cell_rest(Gi1, Gf1, Gg1, Go1, c21);

        // write h2_t into buffer t&1 (read next step after its S2 -> safe)
        if (q == 0) {
            float* h2w = h2b + (t & 1) * 128;
            h2w[h] = h20; h2w[64 + h] = h21;
        }

        // y head partials (wo == 0 on non-base lanes)
        float p0 = h20 * wo;
        float p1 = h21 * wo;
        #pragma unroll
        for (int off = 16; off; off >>= 1) {
            p0 += __shfl_xor_sync(FULL, p0, off);
            p1 += __shfl_xor_sync(FULL, p1, off);
        }
        if (lane == 0) { ybuf[wrp] = p0; ybuf[8 + wrp] = p1; }

        xc0 = xn0; xc1 = xn1;
    }

    __syncthreads();
    if (tid < 2) {   // finalize y_{T-1}
        float s = bo;
        #pragma unroll
        for (int k = 0; k < 8; k++) s += ybuf[tid * 8 + k];
        out[(size_t)(bb + tid) * TT + (TT - 1)] = fminf(fmaxf(s, 0.f), 1.f);
    }
}

extern "C" void kernel_launch(void* const* d_in, const int* in_sizes, int n_in,
                              void* d_out, int out_size)
{
    (void)in_sizes; (void)n_in; (void)out_size;
    const float* x    = (const float*)d_in[0];
    const float* Wih0 = (const float*)d_in[1];
    const float* Whh0 = (const float*)d_in[2];
    const float* bih0 = (const float*)d_in[3];
    const float* bhh0 = (const float*)d_in[4];
    const float* Wih1 = (const float*)d_in[5];
    const float* Whh1 = (const float*)d_in[6];
    const float* bih1 = (const float*)d_in[7];
    const float* bhh1 = (const float*)d_in[8];
    const float* Wout = (const float*)d_in[9];
    const float* bOut = (const float*)d_in[10];
    float* out = (float*)d_out;

    xg_kernel<<<2048, 256>>>(x, Wih0, bih0, bhh0);

    const int smem = 256 * RWSTR * (int)sizeof(ull) + (128 + 256 + 16) * (int)sizeof(float);
    cudaFuncSetAttribute(lstm2_kernel, cudaFuncAttributeMaxDynamicSharedMemorySize, smem);
    lstm2_kernel<<<128, 256, smem>>>(Whh0, Wih1, Whh1, bih1, bhh1, Wout, bOut, out);
}